// round 2
// baseline (speedup 1.0000x reference)
#include <cuda_runtime.h>

// Problem constants (fixed by the reference)
#define T_TOK  4096     // B*S tokens
#define DMODEL 1024
#define DFF    4096
#define NEXP   8
#define TOPK   2

// GEMM tiling
#define BM 128
#define BN 128
#define BK 8
#define TM 8
#define TN 8

// ---------------------------------------------------------------------------
// Scratch (static __device__ arrays; no allocation allowed)
// ---------------------------------------------------------------------------
__device__ int   g_cnt[NEXP];                 // tokens routed to each expert
__device__ int   g_list[NEXP][T_TOK];         // slot ids (t*2+k) per expert
__device__ float g_wt[NEXP][T_TOK];           // renormalized gate weight per entry
__device__ float g_h[(size_t)T_TOK * TOPK * DFF];    // 8192 x 4096 fp32 (134 MB)
__device__ float g_y[(size_t)T_TOK * TOPK * DMODEL]; // 8192 x 1024 fp32 (33 MB)

// ---------------------------------------------------------------------------
// Kernel 0: zero per-expert counters (graph replays need fresh counters)
// ---------------------------------------------------------------------------
__global__ void zero_cnt_kernel() {
    if (threadIdx.x < NEXP) g_cnt[threadIdx.x] = 0;
}

// ---------------------------------------------------------------------------
// Kernel 1: gating. One warp per token.
// logits = x @ Wg; top-2; weights renormalized: w0 = 1/(1+exp(l1-l0)).
// ---------------------------------------------------------------------------
__global__ void gate_kernel(const float* __restrict__ x,
                            const float* __restrict__ Wg) {
    int gwarp = (blockIdx.x * blockDim.x + threadIdx.x) >> 5;
    int lane  = threadIdx.x & 31;
    if (gwarp >= T_TOK) return;
    int t = gwarp;

    const float* xr = x + (size_t)t * DMODEL;
    float acc[NEXP];
#pragma unroll
    for (int e = 0; e < NEXP; e++) acc[e] = 0.f;

    for (int d = lane; d < DMODEL; d += 32) {
        float xv = xr[d];
        const float* wr = Wg + d * NEXP;
#pragma unroll
        for (int e = 0; e < NEXP; e++) acc[e] += xv * wr[e];
    }
#pragma unroll
    for (int e = 0; e < NEXP; e++) {
#pragma unroll
        for (int off = 16; off; off >>= 1)
            acc[e] += __shfl_xor_sync(0xFFFFFFFFu, acc[e], off);
    }
    if (lane == 0) {
        // top-2 (strict > matches jax top_k lowest-index tie-break)
        int i0 = 0; float l0 = acc[0];
#pragma unroll
        for (int e = 1; e < NEXP; e++) if (acc[e] > l0) { l0 = acc[e]; i0 = e; }
        int i1 = -1; float l1 = -3.0e38f;
#pragma unroll
        for (int e = 0; e < NEXP; e++)
            if (e != i0 && acc[e] > l1) { l1 = acc[e]; i1 = e; }

        float w0 = 1.0f / (1.0f + expf(l1 - l0));
        float w1 = 1.0f - w0;

        int p0 = atomicAdd(&g_cnt[i0], 1);
        g_list[i0][p0] = t * 2 + 0; g_wt[i0][p0] = w0;
        int p1 = atomicAdd(&g_cnt[i1], 1);
        g_list[i1][p1] = t * 2 + 1; g_wt[i1][p1] = w1;
    }
}

// ---------------------------------------------------------------------------
// Kernel 2: grouped GEMM1. h[slot] = relu(x[tok] @ W1[e] + b1[e])
// A = gathered x rows [cnt, 1024], B = W1[e] [1024, 4096]
// ---------------------------------------------------------------------------
__global__ __launch_bounds__(256)
void ffn1_kernel(const float* __restrict__ x,
                 const float* __restrict__ W1,
                 const float* __restrict__ b1) {
    const int e     = blockIdx.z;
    const int cnt   = g_cnt[e];
    const int mBase = blockIdx.y * BM;
    if (mBase >= cnt) return;
    const int nBase = blockIdx.x * BN;

    const float* Bp = W1 + (size_t)e * DMODEL * DFF;

    __shared__ float As[BK][BM];
    __shared__ float Bs[BK][BN];

    const int tid  = threadIdx.x;
    const int tr   = tid >> 4;            // 0..15
    const int tc   = tid & 15;            // 0..15
    const int aRow = tid >> 1;            // 0..127
    const int aCol = (tid & 1) * 4;       // 0 or 4
    const int bRow = tid >> 5;            // 0..7
    const int bCol = (tid & 31) * 4;      // 0..124

    const float* arow = nullptr;
    {
        int m = mBase + aRow;
        if (m < cnt) {
            int tok = g_list[e][m] >> 1;
            arow = x + (size_t)tok * DMODEL;
        }
    }

    float acc[TM][TN];
#pragma unroll
    for (int i = 0; i < TM; i++)
#pragma unroll
        for (int j = 0; j < TN; j++) acc[i][j] = 0.f;

    for (int k0 = 0; k0 < DMODEL; k0 += BK) {
        float4 av = arow ? *(const float4*)(arow + k0 + aCol)
                         : make_float4(0.f, 0.f, 0.f, 0.f);
        As[aCol + 0][aRow] = av.x;
        As[aCol + 1][aRow] = av.y;
        As[aCol + 2][aRow] = av.z;
        As[aCol + 3][aRow] = av.w;
        *(float4*)&Bs[bRow][bCol] =
            *(const float4*)(Bp + (size_t)(k0 + bRow) * DFF + nBase + bCol);
        __syncthreads();

#pragma unroll
        for (int k = 0; k < BK; k++) {
            float ra[TM], rb[TN];
            *(float4*)&ra[0] = *(const float4*)&As[k][tr * TM];
            *(float4*)&ra[4] = *(const float4*)&As[k][tr * TM + 4];
            *(float4*)&rb[0] = *(const float4*)&Bs[k][tc * TN];
            *(float4*)&rb[4] = *(const float4*)&Bs[k][tc * TN + 4];
#pragma unroll
            for (int i = 0; i < TM; i++)
#pragma unroll
                for (int j = 0; j < TN; j++)
                    acc[i][j] += ra[i] * rb[j];
        }
        __syncthreads();
    }

    // epilogue: bias + relu -> g_h[slot]
#pragma unroll
    for (int i = 0; i < TM; i++) {
        int mm = mBase + tr * TM + i;
        if (mm < cnt) {
            int slot = g_list[e][mm];
            float* hrow = g_h + (size_t)slot * DFF + nBase + tc * TN;
            const float* brow = b1 + e * DFF + nBase + tc * TN;
#pragma unroll
            for (int j = 0; j < TN; j += 4) {
                float4 v;
                v.x = fmaxf(acc[i][j + 0] + brow[j + 0], 0.f);
                v.y = fmaxf(acc[i][j + 1] + brow[j + 1], 0.f);
                v.z = fmaxf(acc[i][j + 2] + brow[j + 2], 0.f);
                v.w = fmaxf(acc[i][j + 3] + brow[j + 3], 0.f);
                *(float4*)(hrow + j) = v;
            }
        }
    }
}

// ---------------------------------------------------------------------------
// Kernel 3: grouped GEMM2. y[slot] = w * (h[slot] @ W2[e] + b2[e])
// A = gathered h rows [cnt, 4096], B = W2[e] [4096, 1024]
// ---------------------------------------------------------------------------
__global__ __launch_bounds__(256)
void ffn2_kernel(const float* __restrict__ W2,
                 const float* __restrict__ b2) {
    const int e     = blockIdx.z;
    const int cnt   = g_cnt[e];
    const int mBase = blockIdx.y * BM;
    if (mBase >= cnt) return;
    const int nBase = blockIdx.x * BN;

    const float* Bp = W2 + (size_t)e * DFF * DMODEL;

    __shared__ float As[BK][BM];
    __shared__ float Bs[BK][BN];

    const int tid  = threadIdx.x;
    const int tr   = tid >> 4;
    const int tc   = tid & 15;
    const int aRow = tid >> 1;
    const int aCol = (tid & 1) * 4;
    const int bRow = tid >> 5;
    const int bCol = (tid & 31) * 4;

    const float* arow = nullptr;
    {
        int m = mBase + aRow;
        if (m < cnt) {
            int slot = g_list[e][m];
            arow = g_h + (size_t)slot * DFF;
        }
    }

    float acc[TM][TN];
#pragma unroll
    for (int i = 0; i < TM; i++)
#pragma unroll
        for (int j = 0; j < TN; j++) acc[i][j] = 0.f;

    for (int k0 = 0; k0 < DFF; k0 += BK) {
        float4 av = arow ? *(const float4*)(arow + k0 + aCol)
                         : make_float4(0.f, 0.f, 0.f, 0.f);
        As[aCol + 0][aRow] = av.x;
        As[aCol + 1][aRow] = av.y;
        As[aCol + 2][aRow] = av.z;
        As[aCol + 3][aRow] = av.w;
        *(float4*)&Bs[bRow][bCol] =
            *(const float4*)(Bp + (size_t)(k0 + bRow) * DMODEL + nBase + bCol);
        __syncthreads();

#pragma unroll
        for (int k = 0; k < BK; k++) {
            float ra[TM], rb[TN];
            *(float4*)&ra[0] = *(const float4*)&As[k][tr * TM];
            *(float4*)&ra[4] = *(const float4*)&As[k][tr * TM + 4];
            *(float4*)&rb[0] = *(const float4*)&Bs[k][tc * TN];
            *(float4*)&rb[4] = *(const float4*)&Bs[k][tc * TN + 4];
#pragma unroll
            for (int i = 0; i < TM; i++)
#pragma unroll
                for (int j = 0; j < TN; j++)
                    acc[i][j] += ra[i] * rb[j];
        }
        __syncthreads();
    }

    // epilogue: bias, fold gate weight -> g_y[slot]
#pragma unroll
    for (int i = 0; i < TM; i++) {
        int mm = mBase + tr * TM + i;
        if (mm < cnt) {
            int slot = g_list[e][mm];
            float w  = g_wt[e][mm];
            float* yrow = g_y + (size_t)slot * DMODEL + nBase + tc * TN;
            const float* brow = b2 + e * DMODEL + nBase + tc * TN;
#pragma unroll
            for (int j = 0; j < TN; j += 4) {
                float4 v;
                v.x = w * (acc[i][j + 0] + brow[j + 0]);
                v.y = w * (acc[i][j + 1] + brow[j + 1]);
                v.z = w * (acc[i][j + 2] + brow[j + 2]);
                v.w = w * (acc[i][j + 3] + brow[j + 3]);
                *(float4*)(yrow + j) = v;
            }
        }
    }
}

// ---------------------------------------------------------------------------
// Kernel 4: combine. out[t] = y[2t] + y[2t+1]
// ---------------------------------------------------------------------------
__global__ void combine_kernel(float* __restrict__ out) {
    const int VPR = DMODEL / 4;  // float4s per row = 256
    int i = blockIdx.x * blockDim.x + threadIdx.x;
    if (i >= T_TOK * VPR) return;
    int t = i / VPR;
    int c = i % VPR;
    const float4* y4 = (const float4*)g_y;
    float4 a = y4[(size_t)(2 * t) * VPR + c];
    float4 b = y4[(size_t)(2 * t + 1) * VPR + c];
    float4 r;
    r.x = a.x + b.x; r.y = a.y + b.y; r.z = a.z + b.z; r.w = a.w + b.w;
    ((float4*)out)[i] = r;
}

// ---------------------------------------------------------------------------
// Launch
// ---------------------------------------------------------------------------
extern "C" void kernel_launch(void* const* d_in, const int* in_sizes, int n_in,
                              void* d_out, int out_size) {
    const float* x  = (const float*)d_in[0];
    const float* Wg = (const float*)d_in[1];
    const float* W1 = (const float*)d_in[2];
    const float* b1 = (const float*)d_in[3];
    const float* W2 = (const float*)d_in[4];
    const float* b2 = (const float*)d_in[5];
    float* out = (float*)d_out;

    zero_cnt_kernel<<<1, 32>>>();
    gate_kernel<<<T_TOK / 8, 256>>>(x, Wg);   // 8 warps (tokens) per block

    dim3 g1(DFF / BN, T_TOK / BM, NEXP);      // (32, 32, 8); idle m-tiles exit
    ffn1_kernel<<<g1, 256>>>(x, W1, b1);

    dim3 g2(DMODEL / BN, T_TOK / BM, NEXP);   // (8, 32, 8)
    ffn2_kernel<<<g2, 256>>>(W2, b2);

    combine_kernel<<<(T_TOK * (DMODEL / 4) + 255) / 256, 256>>>(out);
}

// round 4
// speedup vs baseline: 1.8509x; 1.8509x over previous
#include <cuda_runtime.h>
#include <cuda_bf16.h>

#define T_TOK  4096
#define DMODEL 1024
#define DFF    4096
#define NEXP   8
#define NSLOT  (T_TOK * 2)

#define BM 128
#define BN 128
#define BK 32                       // K elems per chunk
#define ROWB 80                     // padded row pitch bytes (32 bf16 = 64B + 16B pad)
#define MATB (128 * ROWB)           // 10240 bytes per matrix
#define OFF_AH 0
#define OFF_AL (1 * MATB)
#define OFF_BH (2 * MATB)
#define OFF_BL (3 * MATB)
#define STAGE_BYTES (4 * MATB)      // 40960
#define SMEM_TOTAL (2 * STAGE_BYTES)  // 81920 (epilogue reuses: 128*132*4 = 67584)
#define EPITCH 132                  // fp32 epilogue row pitch (words)

// ---------------------------------------------------------------------------
// Scratch
// ---------------------------------------------------------------------------
__device__ int   g_cnt[NEXP];
__device__ int   g_list[NEXP][T_TOK];
__device__ float g_wt[NEXP][T_TOK];
__device__ __nv_bfloat16 g_x_hi[(size_t)T_TOK * DMODEL];
__device__ __nv_bfloat16 g_x_lo[(size_t)T_TOK * DMODEL];
__device__ __nv_bfloat16 g_w1_hi[(size_t)NEXP * DFF * DMODEL];   // [e][f][d]
__device__ __nv_bfloat16 g_w1_lo[(size_t)NEXP * DFF * DMODEL];
__device__ __nv_bfloat16 g_w2_hi[(size_t)NEXP * DMODEL * DFF];   // [e][d][f]
__device__ __nv_bfloat16 g_w2_lo[(size_t)NEXP * DMODEL * DFF];
__device__ __nv_bfloat16 g_h_hi[(size_t)NSLOT * DFF];
__device__ __nv_bfloat16 g_h_lo[(size_t)NSLOT * DFF];
__device__ float g_y[(size_t)NSLOT * DMODEL];

// ---------------------------------------------------------------------------
// PTX helpers (all target-portable: sm_80-class PTX only)
// ---------------------------------------------------------------------------
__device__ __forceinline__ unsigned smem_u32(const void* p) {
    unsigned a;
    asm("{ .reg .u64 t; cvta.to.shared.u64 t, %1; cvt.u32.u64 %0, t; }"
        : "=r"(a) : "l"(p));
    return a;
}
__device__ __forceinline__ void cp16(unsigned d, const void* s) {
    asm volatile("cp.async.cg.shared.global [%0], [%1], 16;"
                 :: "r"(d), "l"(s) : "memory");
}
__device__ __forceinline__ void cp_commit() {
    asm volatile("cp.async.commit_group;" ::: "memory");
}
template<int N> __device__ __forceinline__ void cp_wait() {
    asm volatile("cp.async.wait_group %0;" :: "n"(N) : "memory");
}
__device__ __forceinline__ uint4 ldsm4(unsigned a) {
    uint4 r;
    asm volatile("ldmatrix.sync.aligned.m8n8.x4.shared.b16 {%0,%1,%2,%3}, [%4];"
                 : "=r"(r.x), "=r"(r.y), "=r"(r.z), "=r"(r.w) : "r"(a));
    return r;
}
__device__ __forceinline__ void mma16816(float* c, const uint4& a,
                                         unsigned b0, unsigned b1) {
    asm volatile(
        "mma.sync.aligned.m16n8k16.row.col.f32.bf16.bf16.f32 "
        "{%0,%1,%2,%3},{%4,%5,%6,%7},{%8,%9},{%0,%1,%2,%3};"
        : "+f"(c[0]), "+f"(c[1]), "+f"(c[2]), "+f"(c[3])
        : "r"(a.x), "r"(a.y), "r"(a.z), "r"(a.w), "r"(b0), "r"(b1));
}
__device__ __forceinline__ void bsplit(float v, unsigned short& h, unsigned short& l) {
    __nv_bfloat16 b = __float2bfloat16(v);
    h = __bfloat16_as_ushort(b);
    l = __bfloat16_as_ushort(__float2bfloat16(v - __bfloat162float(b)));
}

// ---------------------------------------------------------------------------
// Small kernels
// ---------------------------------------------------------------------------
__global__ void zero_cnt_kernel() {
    if (threadIdx.x < NEXP) g_cnt[threadIdx.x] = 0;
}

__global__ void gate_kernel(const float* __restrict__ x,
                            const float* __restrict__ Wg) {
    int gwarp = (blockIdx.x * blockDim.x + threadIdx.x) >> 5;
    int lane  = threadIdx.x & 31;
    if (gwarp >= T_TOK) return;
    int t = gwarp;
    const float* xr = x + (size_t)t * DMODEL;
    float acc[NEXP];
#pragma unroll
    for (int e = 0; e < NEXP; e++) acc[e] = 0.f;
    for (int d = lane; d < DMODEL; d += 32) {
        float xv = xr[d];
        const float* wr = Wg + d * NEXP;
#pragma unroll
        for (int e = 0; e < NEXP; e++) acc[e] += xv * wr[e];
    }
#pragma unroll
    for (int e = 0; e < NEXP; e++)
#pragma unroll
        for (int off = 16; off; off >>= 1)
            acc[e] += __shfl_xor_sync(0xFFFFFFFFu, acc[e], off);
    if (lane == 0) {
        int i0 = 0; float l0 = acc[0];
#pragma unroll
        for (int e = 1; e < NEXP; e++) if (acc[e] > l0) { l0 = acc[e]; i0 = e; }
        int i1 = -1; float l1 = -3.0e38f;
#pragma unroll
        for (int e = 0; e < NEXP; e++)
            if (e != i0 && acc[e] > l1) { l1 = acc[e]; i1 = e; }
        float w0 = 1.0f / (1.0f + expf(l1 - l0));
        float w1 = 1.0f - w0;
        int p0 = atomicAdd(&g_cnt[i0], 1);
        g_list[i0][p0] = t * 2 + 0; g_wt[i0][p0] = w0;
        int p1 = atomicAdd(&g_cnt[i1], 1);
        g_list[i1][p1] = t * 2 + 1; g_wt[i1][p1] = w1;
    }
}

__global__ void split_x_kernel(const float* __restrict__ x) {
    size_t i = ((size_t)blockIdx.x * blockDim.x + threadIdx.x) * 4;
    float4 v = *(const float4*)(x + i);
    ushort4 h, l;
    bsplit(v.x, h.x, l.x); bsplit(v.y, h.y, l.y);
    bsplit(v.z, h.z, l.z); bsplit(v.w, h.w, l.w);
    *(ushort4*)(g_x_hi + i) = h;
    *(ushort4*)(g_x_lo + i) = l;
}

// transpose + hi/lo split: in [R][C] fp32 per expert -> out [C][R] bf16
template<int WSEL>
__global__ void transp_split_kernel(const float* __restrict__ in) {
    const int R = (WSEL == 0) ? DMODEL : DFF;
    const int C = (WSEL == 0) ? DFF : DMODEL;
    __nv_bfloat16* ohi = (WSEL == 0) ? g_w1_hi : g_w2_hi;
    __nv_bfloat16* olo = (WSEL == 0) ? g_w1_lo : g_w2_lo;
    __shared__ float t[32][33];
    size_t eb = (size_t)blockIdx.z * R * C;
    int c0 = blockIdx.x * 32, r0 = blockIdx.y * 32;
    int tx = threadIdx.x, ty = threadIdx.y;
    for (int i = ty; i < 32; i += 8)
        t[i][tx] = in[eb + (size_t)(r0 + i) * C + c0 + tx];
    __syncthreads();
    for (int i = ty; i < 32; i += 8) {
        float v = t[tx][i];
        unsigned short h, l;
        bsplit(v, h, l);
        size_t o = eb + (size_t)(c0 + i) * R + r0 + tx;
        ohi[o] = __ushort_as_bfloat16(h);
        olo[o] = __ushort_as_bfloat16(l);
    }
}

__global__ void combine_kernel(float* __restrict__ out) {
    const int VPR = DMODEL / 4;
    int i = blockIdx.x * blockDim.x + threadIdx.x;
    if (i >= T_TOK * VPR) return;
    int t = i / VPR, c = i % VPR;
    const float4* y4 = (const float4*)g_y;
    float4 a = y4[(size_t)(2 * t) * VPR + c];
    float4 b = y4[(size_t)(2 * t + 1) * VPR + c];
    float4 r;
    r.x = a.x + b.x; r.y = a.y + b.y; r.z = a.z + b.z; r.w = a.w + b.w;
    ((float4*)out)[i] = r;
}

// ---------------------------------------------------------------------------
// Grouped GEMM via mma.sync (HMMA), hi/lo bf16 split, 3 terms.
// MODE 0: A=g_x (token rows), B=g_w1 -> h = relu(acc + b1) stored hi/lo bf16
// MODE 1: A=g_h (slot rows),  B=g_w2 -> y = wt * (acc + b2) stored fp32
// ---------------------------------------------------------------------------
template<int KTOT, int NTOT, int MODE>
__global__ void __launch_bounds__(256, 1)
moe_gemm_kernel(const float* __restrict__ bias) {
    extern __shared__ __align__(128) char smem[];
    const int e   = blockIdx.z;
    const int cnt = g_cnt[e];
    const int mB  = blockIdx.y * BM;
    if (mB >= cnt) return;
    const int nB  = blockIdx.x * BN;
    const int tid = threadIdx.x;
    const int lane = tid & 31;
    const int wid  = tid >> 5;
    const int warp_m = wid & 3;     // 4 warps along M (32 rows each)
    const int warp_n = wid >> 2;    // 2 warps along N (64 cols each)
    const int NCH = KTOT / BK;

    const __nv_bfloat16* Ahi = (MODE == 0) ? g_x_hi : g_h_hi;
    const __nv_bfloat16* Alo = (MODE == 0) ? g_x_lo : g_h_lo;
    const __nv_bfloat16* Bhi = (MODE == 0) ? g_w1_hi : g_w2_hi;
    const __nv_bfloat16* Blo = (MODE == 0) ? g_w1_lo : g_w2_lo;

    const unsigned sbase = smem_u32(smem);

    // ---- copy lane setup: thread t loads row (t>>1), 32B seg (t&1) of each matrix
    const int crow = tid >> 1;
    const int cseg = (tid & 1) * 32;
    const char *pAH, *pAL, *pBH, *pBL;
    {
        int m = mB + crow;
        int ar = 0;
        if (m < cnt) { int s = g_list[e][m]; ar = (MODE == 0) ? (s >> 1) : s; }
        pAH = (const char*)(Ahi + (size_t)ar * KTOT) + cseg;
        pAL = (const char*)(Alo + (size_t)ar * KTOT) + cseg;
        size_t bo = (size_t)e * NTOT * KTOT + (size_t)(nB + crow) * KTOT;
        pBH = (const char*)(Bhi + bo) + cseg;
        pBL = (const char*)(Blo + bo) + cseg;
    }
    const unsigned cdst = crow * ROWB + cseg;

#define LOADC(s, c) do { \
        unsigned st_ = sbase + (s) * STAGE_BYTES + cdst; \
        size_t ko_ = (size_t)(c) * (BK * 2); \
        cp16(st_ + OFF_AH,      pAH + ko_); \
        cp16(st_ + OFF_AH + 16, pAH + ko_ + 16); \
        cp16(st_ + OFF_AL,      pAL + ko_); \
        cp16(st_ + OFF_AL + 16, pAL + ko_ + 16); \
        cp16(st_ + OFF_BH,      pBH + ko_); \
        cp16(st_ + OFF_BH + 16, pBH + ko_ + 16); \
        cp16(st_ + OFF_BL,      pBL + ko_); \
        cp16(st_ + OFF_BL + 16, pBL + ko_ + 16); \
    } while (0)

    // ---- ldmatrix lane offsets (within a matrix, before ks/stage offset)
    unsigned aoff[2], boff[4];
#pragma unroll
    for (int mt = 0; mt < 2; mt++)
        aoff[mt] = (unsigned)(warp_m * 32 + mt * 16 + (lane & 15)) * ROWB
                 + (unsigned)((lane >> 4) * 8) * 2;
#pragma unroll
    for (int p = 0; p < 4; p++)
        boff[p] = (unsigned)(warp_n * 64 + p * 16 + ((lane >> 4) << 3) + (lane & 7)) * ROWB
                + (unsigned)(((lane >> 3) & 1) * 8) * 2;

    float acc[2][8][4];
#pragma unroll
    for (int i = 0; i < 2; i++)
#pragma unroll
        for (int j = 0; j < 8; j++)
#pragma unroll
            for (int q = 0; q < 4; q++) acc[i][j][q] = 0.f;

    LOADC(0, 0);
    cp_commit();

    for (int c = 0; c < NCH; c++) {
        if (c + 1 < NCH) {
            LOADC((c + 1) & 1, c + 1);
            cp_commit();
            cp_wait<1>();
        } else {
            cp_wait<0>();
        }
        __syncthreads();

        const unsigned st = sbase + (c & 1) * STAGE_BYTES;
#pragma unroll
        for (int ks = 0; ks < 2; ks++) {
            const unsigned ko = ks * 32;   // 16 bf16 = 32 bytes
            uint4 ah[2], al[2];
#pragma unroll
            for (int mt = 0; mt < 2; mt++) {
                ah[mt] = ldsm4(st + OFF_AH + aoff[mt] + ko);
                al[mt] = ldsm4(st + OFF_AL + aoff[mt] + ko);
            }
            uint4 bh[4], bl[4];
#pragma unroll
            for (int p = 0; p < 4; p++) {
                bh[p] = ldsm4(st + OFF_BH + boff[p] + ko);
                bl[p] = ldsm4(st + OFF_BL + boff[p] + ko);
            }
#pragma unroll
            for (int mt = 0; mt < 2; mt++)
#pragma unroll
                for (int p = 0; p < 4; p++) {
                    float* c0 = acc[mt][2 * p];
                    float* c1 = acc[mt][2 * p + 1];
                    mma16816(c0, ah[mt], bh[p].x, bh[p].y);
                    mma16816(c0, al[mt], bh[p].x, bh[p].y);
                    mma16816(c0, ah[mt], bl[p].x, bl[p].y);
                    mma16816(c1, ah[mt], bh[p].z, bh[p].w);
                    mma16816(c1, al[mt], bh[p].z, bh[p].w);
                    mma16816(c1, ah[mt], bl[p].z, bl[p].w);
                }
        }
        __syncthreads();
    }

    // ---------------- epilogue: acc -> smem fp32 -> global ----------------
    float* ep = (float*)smem;
    {
        int g = lane >> 2, q4 = lane & 3;
#pragma unroll
        for (int mt = 0; mt < 2; mt++) {
            int r0 = warp_m * 32 + mt * 16 + g;
#pragma unroll
            for (int nt = 0; nt < 8; nt++) {
                int cc = warp_n * 64 + nt * 8 + q4 * 2;
                *(float2*)&ep[(size_t)r0 * EPITCH + cc] =
                    make_float2(acc[mt][nt][0], acc[mt][nt][1]);
                *(float2*)&ep[(size_t)(r0 + 8) * EPITCH + cc] =
                    make_float2(acc[mt][nt][2], acc[mt][nt][3]);
            }
        }
    }
    __syncthreads();

    {
        int r = tid >> 1;
        int m = mB + r;
        if (m < cnt) {
            int slot = g_list[e][m];
            int c0 = (tid & 1) * 64;
            const float* row = ep + (size_t)r * EPITCH + c0;
            const float* bp = bias + (size_t)e * NTOT + nB + c0;
            if (MODE == 0) {
                __nv_bfloat16* dh = g_h_hi + (size_t)slot * NTOT + nB + c0;
                __nv_bfloat16* dl = g_h_lo + (size_t)slot * NTOT + nB + c0;
#pragma unroll
                for (int g2 = 0; g2 < 8; g2++) {
                    ushort4 hv, lv;
                    unsigned short h, l;
#pragma unroll
                    for (int j = 0; j < 8; j++) {
                        float v = fmaxf(row[g2 * 8 + j] + bp[g2 * 8 + j], 0.f);
                        bsplit(v, h, l);
                        ((unsigned short*)&hv)[j & 3] = h;
                        ((unsigned short*)&lv)[j & 3] = l;
                        if ((j & 3) == 3) {
                            *(ushort4*)(dh + g2 * 8 + j - 3) = hv;
                            *(ushort4*)(dl + g2 * 8 + j - 3) = lv;
                        }
                    }
                }
            } else {
                float w = g_wt[e][m];
                float* dy = g_y + (size_t)slot * NTOT + nB + c0;
#pragma unroll
                for (int g2 = 0; g2 < 16; g2++) {
                    float4 v;
                    v.x = w * (row[g2 * 4 + 0] + bp[g2 * 4 + 0]);
                    v.y = w * (row[g2 * 4 + 1] + bp[g2 * 4 + 1]);
                    v.z = w * (row[g2 * 4 + 2] + bp[g2 * 4 + 2]);
                    v.w = w * (row[g2 * 4 + 3] + bp[g2 * 4 + 3]);
                    *(float4*)(dy + g2 * 4) = v;
                }
            }
        }
    }
}

// ---------------------------------------------------------------------------
// Launch
// ---------------------------------------------------------------------------
extern "C" void kernel_launch(void* const* d_in, const int* in_sizes, int n_in,
                              void* d_out, int out_size) {
    const float* x  = (const float*)d_in[0];
    const float* Wg = (const float*)d_in[1];
    const float* W1 = (const float*)d_in[2];
    const float* b1 = (const float*)d_in[3];
    const float* W2 = (const float*)d_in[4];
    const float* b2 = (const float*)d_in[5];
    float* out = (float*)d_out;

    cudaFuncSetAttribute(moe_gemm_kernel<DMODEL, DFF, 0>,
                         cudaFuncAttributeMaxDynamicSharedMemorySize, SMEM_TOTAL);
    cudaFuncSetAttribute(moe_gemm_kernel<DFF, DMODEL, 1>,
                         cudaFuncAttributeMaxDynamicSharedMemorySize, SMEM_TOTAL);

    zero_cnt_kernel<<<1, 32>>>();
    gate_kernel<<<T_TOK / 8, 256>>>(x, Wg);
    split_x_kernel<<<(T_TOK * DMODEL) / 4 / 256, 256>>>(x);

    dim3 tb(32, 8);
    transp_split_kernel<0><<<dim3(DFF / 32, DMODEL / 32, NEXP), tb>>>(W1);
    transp_split_kernel<1><<<dim3(DMODEL / 32, DFF / 32, NEXP), tb>>>(W2);

    moe_gemm_kernel<DMODEL, DFF, 0>
        <<<dim3(DFF / BN, T_TOK / BM, NEXP), 256, SMEM_TOTAL>>>(b1);
    moe_gemm_kernel<DFF, DMODEL, 1>
        <<<dim3(DMODEL / BN, T_TOK / BM, NEXP), 256, SMEM_TOTAL>>>(b2);

    combine_kernel<<<(T_TOK * (DMODEL / 4) + 255) / 256, 256>>>(out);
}